// round 3
// baseline (speedup 1.0000x reference)
#include <cuda_runtime.h>
#include <math.h>

typedef unsigned long long u64;

__device__ __forceinline__ u64 f2pk(float lo, float hi) {
    u64 r; asm("mov.b64 %0,{%1,%2};" : "=l"(r) : "f"(lo), "f"(hi)); return r;
}
__device__ __forceinline__ void f2upk(u64 a, float& lo, float& hi) {
    asm("mov.b64 {%0,%1},%2;" : "=f"(lo), "=f"(hi) : "l"(a));
}
__device__ __forceinline__ u64 f2add(u64 a, u64 b) {
    u64 d; asm("add.rn.f32x2 %0,%1,%2;" : "=l"(d) : "l"(a), "l"(b)); return d;
}
__device__ __forceinline__ u64 f2mul(u64 a, u64 b) {
    u64 d; asm("mul.rn.f32x2 %0,%1,%2;" : "=l"(d) : "l"(a), "l"(b)); return d;
}
__device__ __forceinline__ u64 f2fma(u64 a, u64 b, u64 c) {
    u64 d; asm("fma.rn.f32x2 %0,%1,%2,%3;" : "=l"(d) : "l"(a), "l"(b), "l"(c)); return d;
}

// MLP 6->20->20->20->8, tanh. Weights in smem.
__device__ __forceinline__ void mlp(const float Z[6], float z[8],
    const float* sW1, const float* sb1, const float* sW2, const float* sb2,
    const float* sW3, const float* sb3, const float* sW4, const float* sb4)
{
    float h1[20], h2[20];
#pragma unroll
    for (int o = 0; o < 20; ++o) {
        const float2* w = reinterpret_cast<const float2*>(&sW1[o * 6]);
        float2 w0 = w[0], w1 = w[1], w2 = w[2];
        float a = sb1[o];
        a = fmaf(w0.x, Z[0], a); a = fmaf(w0.y, Z[1], a);
        a = fmaf(w1.x, Z[2], a); a = fmaf(w1.y, Z[3], a);
        a = fmaf(w2.x, Z[4], a); a = fmaf(w2.y, Z[5], a);
        h1[o] = tanhf(a);
    }
#pragma unroll
    for (int o = 0; o < 20; ++o) {
        const float4* w = reinterpret_cast<const float4*>(&sW2[o * 20]);
        float a = sb2[o];
#pragma unroll
        for (int q = 0; q < 5; ++q) {
            float4 wq = w[q];
            a = fmaf(wq.x, h1[q * 4 + 0], a);
            a = fmaf(wq.y, h1[q * 4 + 1], a);
            a = fmaf(wq.z, h1[q * 4 + 2], a);
            a = fmaf(wq.w, h1[q * 4 + 3], a);
        }
        h2[o] = tanhf(a);
    }
#pragma unroll
    for (int o = 0; o < 20; ++o) {
        const float4* w = reinterpret_cast<const float4*>(&sW3[o * 20]);
        float a = sb3[o];
#pragma unroll
        for (int q = 0; q < 5; ++q) {
            float4 wq = w[q];
            a = fmaf(wq.x, h2[q * 4 + 0], a);
            a = fmaf(wq.y, h2[q * 4 + 1], a);
            a = fmaf(wq.z, h2[q * 4 + 2], a);
            a = fmaf(wq.w, h2[q * 4 + 3], a);
        }
        h1[o] = tanhf(a);
    }
#pragma unroll
    for (int o = 0; o < 8; ++o) {
        const float4* w = reinterpret_cast<const float4*>(&sW4[o * 20]);
        float a = sb4[o];
#pragma unroll
        for (int q = 0; q < 5; ++q) {
            float4 wq = w[q];
            a = fmaf(wq.x, h1[q * 4 + 0], a);
            a = fmaf(wq.y, h1[q * 4 + 1], a);
            a = fmaf(wq.z, h1[q * 4 + 2], a);
            a = fmaf(wq.w, h1[q * 4 + 3], a);
        }
        z[o] = tanhf(a);
    }
}

__global__ void __launch_bounds__(128, 1) matchnet_kernel(
    const float* __restrict__ X,
    const float* __restrict__ W1, const float* __restrict__ b1,
    const float* __restrict__ W2, const float* __restrict__ b2,
    const float* __restrict__ W3, const float* __restrict__ b3,
    const float* __restrict__ W4, const float* __restrict__ b4,
    float* __restrict__ out, int B)
{
    __shared__ __align__(16) float sW1[120];
    __shared__ __align__(16) float sW2[400];
    __shared__ __align__(16) float sW3[400];
    __shared__ __align__(16) float sW4[160];
    __shared__ float sb1[20], sb2s[20], sb3[20], sb4[8];

    const int t = threadIdx.x;
    for (int i = t; i < 120; i += 128) sW1[i] = W1[i];
    for (int i = t; i < 400; i += 128) sW2[i] = W2[i];
    for (int i = t; i < 400; i += 128) sW3[i] = W3[i];
    for (int i = t; i < 160; i += 128) sW4[i] = W4[i];
    if (t < 20) { sb1[t] = b1[t]; sb2s[t] = b2[t]; sb3[t] = b3[t]; }
    if (t < 8)  { sb4[t] = b4[t]; }
    __syncthreads();

    const int half = B >> 1;
    const int i0 = blockIdx.x * 128 + t;   // sample A
    const int i1 = i0 + half;              // sample B
    if (i0 >= half) return;

    // ---- load bids for both samples ----
    float Za[2][6];
#pragma unroll
    for (int s = 0; s < 2; ++s) {
        const int id = (s == 0) ? i0 : i1;
        const float2* Xp = reinterpret_cast<const float2*>(X + (size_t)id * 6);
        float2 a0 = Xp[0], a1 = Xp[1], a2 = Xp[2];
        Za[s][0] = a0.x; Za[s][1] = a0.y; Za[s][2] = a1.x;
        Za[s][3] = a1.y; Za[s][4] = a2.x; Za[s][5] = a2.y;
    }

    // ---- MLPs (sequential to cap register pressure) ----
    float zz[2][8];
    mlp(Za[0], zz[0], sW1, sb1, sW2, sb2s, sW3, sb3, sW4, sb4);
    mlp(Za[1], zz[1], sW1, sb1, sW2, sb2s, sW3, sb3, sW4, sb4);

    // ---- PDHG QP (packed f32x2), 2 independent chains per thread ----
    const float tau  = 0.9f / sqrtf(26.0f);
    const float tau2 = tau * tau;
    const u64 NEG1 = 0xBF800000BF800000ULL;
    const u64 NT2  = f2pk(-tau2, -tau2);

    u64 zp[2][4], czp[2][4], sb2p[2][3], xp[2][4], l2p[2][4];
    float m[2][6];
#pragma unroll
    for (int s = 0; s < 2; ++s) {
#pragma unroll
        for (int k = 0; k < 4; ++k) {
            float zl = zz[s][2 * k], zh = zz[s][2 * k + 1];
            zp[s][k]  = f2pk(zl, zh);
            czp[s][k] = f2pk(tau - zl, tau - zh);
            xp[s][k]  = f2pk(fmaxf(zl, 0.0f), fmaxf(zh, 0.0f));
            l2p[s][k] = 0ULL;
        }
        sb2p[s][0] = f2pk(tau2 * Za[s][0], tau2 * Za[s][1]);
        sb2p[s][1] = f2pk(tau2 * Za[s][2], tau2 * Za[s][3]);
        sb2p[s][2] = f2pk(tau2 * Za[s][4], tau2 * Za[s][5]);
#pragma unroll
        for (int i = 0; i < 6; ++i) m[s][i] = 0.0f;
    }

#pragma unroll 1
    for (int it = 0; it < 150; ++it) {
#pragma unroll
        for (int s = 0; s < 2; ++s) {
            float m0 = m[s][0], m1 = m[s][1], m2 = m[s][2];
            float m3 = m[s][3], m4 = m[s][4], m5 = m[s][5];

            // sv'' = -tau * S^T l1 (<=0), packed pairs
            u64 s01 = f2add(f2pk(m0, m1), f2pk(m3, m4));       // (sv0, sv1)
            float t01 = m0 + m1;
            u64 s23 = f2add(f2pk(m2, t01), f2pk(m5, m5));      // (sv2, sv3)
            float t23 = m2 + m3;
            float sv4 = t23 + m5;
            float sv0, sv1; f2upk(s01, sv0, sv1);
            u64 s45 = f2pk(sv4, sv0);                          // (sv4, sv5=sv0)
            u64 s67 = f2add(f2pk(m1, m2), f2pk(m4, m4));       // (sv6=sv1, sv7)

            // v = (x + cz) + (L2' + sv'')
            u64 v0 = f2add(f2add(xp[s][0], czp[s][0]), f2add(l2p[s][0], s01));
            u64 v1 = f2add(f2add(xp[s][1], czp[s][1]), f2add(l2p[s][1], s23));
            u64 v2 = f2add(f2add(xp[s][2], czp[s][2]), f2add(l2p[s][2], s45));
            u64 v3 = f2add(f2add(xp[s][3], czp[s][3]), f2add(l2p[s][3], s67));

            // ||v||^2
            u64 nm = f2mul(v0, v0);
            nm = f2fma(v1, v1, nm);
            nm = f2fma(v2, v2, nm);
            nm = f2fma(v3, v3, nm);
            float na, nb; f2upk(nm, na, nb);
            float ss = na + nb;

            float r = rsqrtf(ss);
            float scale = fmaxf(fmaf(-tau, r, 1.0f), 0.0f);
            u64 sc2 = f2pk(scale, scale);

            // xn = z + scale*v ; xb = 2*xn - x
            u64 xn0 = f2fma(v0, sc2, zp[s][0]);
            u64 xn1 = f2fma(v1, sc2, zp[s][1]);
            u64 xn2 = f2fma(v2, sc2, zp[s][2]);
            u64 xn3 = f2fma(v3, sc2, zp[s][3]);
            u64 xb0 = f2add(xn0, f2fma(xp[s][0], NEG1, xn0));
            u64 xb1 = f2add(xn1, f2fma(xp[s][1], NEG1, xn1));
            u64 xb2 = f2add(xn2, f2fma(xp[s][2], NEG1, xn2));
            u64 xb3 = f2add(xn3, f2fma(xp[s][3], NEG1, xn3));
            xp[s][0] = xn0; xp[s][1] = xn1; xp[s][2] = xn2; xp[s][3] = xn3;

            float e0, e1, e2, e3, e4, e5, e6, e7;
            f2upk(xb0, e0, e1); f2upk(xb1, e2, e3);
            f2upk(xb2, e4, e5); f2upk(xb3, e6, e7);

            // rr = S @ xb
            u64 pp = f2add(xb0, f2pk(e5, e6));                 // (p05, p16)
            float p05, p16; f2upk(pp, p05, p16);
            float p24 = e2 + e4;
            u64 rr01 = f2add(pp, f2pk(e3, e3));                // (rr0, rr1)
            u64 rr23 = f2add(f2pk(p24, p05), f2pk(e7, e4));    // (rr2, rr3)
            u64 rr45 = f2add(f2pk(p16, p24), f2pk(e7, e3));    // (rr4, rr5)

            // l1 dual (negated, scaled): m = min(m - tau2*rr + tau2*b, 0)
            u64 u01 = f2add(f2fma(rr01, NT2, f2pk(m0, m1)), sb2p[s][0]);
            u64 u23 = f2add(f2fma(rr23, NT2, f2pk(m2, m3)), sb2p[s][1]);
            u64 u45 = f2add(f2fma(rr45, NT2, f2pk(m4, m5)), sb2p[s][2]);
            float q0, q1, q2, q3, q4, q5;
            f2upk(u01, q0, q1); f2upk(u23, q2, q3); f2upk(u45, q4, q5);
            m[s][0] = fminf(q0, 0.0f); m[s][1] = fminf(q1, 0.0f);
            m[s][2] = fminf(q2, 0.0f); m[s][3] = fminf(q3, 0.0f);
            m[s][4] = fminf(q4, 0.0f); m[s][5] = fminf(q5, 0.0f);

            // l2 dual (scaled): L2' = max(L2' - tau2*xb, 0)
            {
                u64 w0 = f2fma(xb0, NT2, l2p[s][0]);
                u64 w1 = f2fma(xb1, NT2, l2p[s][1]);
                u64 w2 = f2fma(xb2, NT2, l2p[s][2]);
                u64 w3 = f2fma(xb3, NT2, l2p[s][3]);
                float a, b;
                f2upk(w0, a, b); l2p[s][0] = f2pk(fmaxf(a, 0.f), fmaxf(b, 0.f));
                f2upk(w1, a, b); l2p[s][1] = f2pk(fmaxf(a, 0.f), fmaxf(b, 0.f));
                f2upk(w2, a, b); l2p[s][2] = f2pk(fmaxf(a, 0.f), fmaxf(b, 0.f));
                f2upk(w3, a, b); l2p[s][3] = f2pk(fmaxf(a, 0.f), fmaxf(b, 0.f));
            }
        }
    }

#pragma unroll
    for (int s = 0; s < 2; ++s) {
        const int id = (s == 0) ? i0 : i1;
        float o0, o1, o2, o3, o4, o5, o6, o7;
        f2upk(xp[s][0], o0, o1); f2upk(xp[s][1], o2, o3);
        f2upk(xp[s][2], o4, o5); f2upk(xp[s][3], o6, o7);
        float4* op = reinterpret_cast<float4*>(out + (size_t)id * 8);
        op[0] = make_float4(o0, o1, o2, o3);
        op[1] = make_float4(o4, o5, o6, o7);
    }
}

extern "C" void kernel_launch(void* const* d_in, const int* in_sizes, int n_in,
                              void* d_out, int out_size)
{
    const float* X  = (const float*)d_in[0];
    const float* W1 = (const float*)d_in[1];
    const float* b1 = (const float*)d_in[2];
    const float* W2 = (const float*)d_in[3];
    const float* b2 = (const float*)d_in[4];
    const float* W3 = (const float*)d_in[5];
    const float* b3 = (const float*)d_in[6];
    const float* W4 = (const float*)d_in[7];
    const float* b4 = (const float*)d_in[8];

    const int B = in_sizes[0] / 6;
    float* out = (float*)d_out;

    const int threads = B / 2;               // 2 samples per thread
    const int block = 128;
    const int grid = (threads + block - 1) / block;
    matchnet_kernel<<<grid, block>>>(X, W1, b1, W2, b2, W3, b3, W4, b4, out, B);
}